// round 16
// baseline (speedup 1.0000x reference)
#include <cuda_runtime.h>
#include <cuda_fp16.h>
#include <cstdint>

#define BATCH 8
#define CIN   192
#define NPIX  4096
#define LAT   96
// log2(e) / sqrt(96): fold softmax scale + base-2 exp into K
#define SCALE_K 0.14724450f

// Static device scratch (allocation-free) — fp16
__device__ __half g_qk[(size_t)BATCH * NPIX * 192]; // [b][n][0:96=Q, 96:192=K*SCALE_K]
__device__ __half g_v [(size_t)BATCH * LAT * NPIX]; // [b][c][n]

// ---------------------------------------------------------------------------
// helpers
// ---------------------------------------------------------------------------
__device__ __forceinline__ void mma16(float d[4], const uint32_t a[4], const uint32_t b[2]) {
    asm volatile(
        "mma.sync.aligned.m16n8k16.row.col.f32.f16.f16.f32 "
        "{%0,%1,%2,%3}, {%4,%5,%6,%7}, {%8,%9}, {%0,%1,%2,%3};"
        : "+f"(d[0]), "+f"(d[1]), "+f"(d[2]), "+f"(d[3])
        : "r"(a[0]), "r"(a[1]), "r"(a[2]), "r"(a[3]), "r"(b[0]), "r"(b[1]));
}
__device__ __forceinline__ void mma16h(uint32_t d[2], const uint32_t a[4], const uint32_t b[2]) {
    asm volatile(
        "mma.sync.aligned.m16n8k16.row.col.f16.f16.f16.f16 "
        "{%0,%1}, {%2,%3,%4,%5}, {%6,%7}, {%0,%1};"
        : "+r"(d[0]), "+r"(d[1])
        : "r"(a[0]), "r"(a[1]), "r"(a[2]), "r"(a[3]), "r"(b[0]), "r"(b[1]));
}
__device__ __forceinline__ void ldsm4(uint32_t r[4], uint32_t addr) {
    asm volatile("ldmatrix.sync.aligned.m8n8.x4.shared.b16 {%0,%1,%2,%3}, [%4];"
        : "=r"(r[0]), "=r"(r[1]), "=r"(r[2]), "=r"(r[3]) : "r"(addr));
}
__device__ __forceinline__ float frcp(float x) {
    float r; asm("rcp.approx.ftz.f32 %0, %1;" : "=f"(r) : "f"(x));
    return r * (2.0f - x * r);
}
__device__ __forceinline__ uint32_t pack_h(float lo, float hi) {
    __half2 h = __floats2half2_rn(lo, hi);
    return *reinterpret_cast<uint32_t*>(&h);
}
__device__ __forceinline__ uint32_t hex2(uint32_t a) {
    uint32_t r; asm("ex2.approx.f16x2 %0, %1;" : "=r"(r) : "r"(a)); return r;
}
__device__ __forceinline__ uint32_t hadd2(uint32_t a, uint32_t b) {
    uint32_t r; asm("add.f16x2 %0, %1, %2;" : "=r"(r) : "r"(a), "r"(b)); return r;
}
__device__ __forceinline__ float h2sum(uint32_t a) {
    __half2 h = *reinterpret_cast<__half2*>(&a);
    return __low2float(h) + __high2float(h);
}
__device__ __forceinline__ void cpa16(void* dst, const void* src) {
    uint32_t d = (uint32_t)__cvta_generic_to_shared(dst);
    asm volatile("cp.async.cg.shared.global [%0], [%1], 16;" :: "r"(d), "l"(src));
}
#define CP_COMMIT() asm volatile("cp.async.commit_group;")
#define CP_WAIT0()  asm volatile("cp.async.wait_group 0;")
__device__ __forceinline__ float rsum4(float v) {
    v += __shfl_xor_sync(0xffffffffu, v, 1);
    v += __shfl_xor_sync(0xffffffffu, v, 2);
    return v;
}

// ---------------------------------------------------------------------------
// Kernel 1: projection t = Wt@x + bt (fp16 mma, fp32 accum). (unchanged)
// ---------------------------------------------------------------------------
#define PJS 100
#define PROJ_SMEM_BYTES ((128 * PJS + 96 * PJS) * 4)   // 89600

__global__ __launch_bounds__(256, 2) void proj_kernel(
    const float* __restrict__ x, const float* __restrict__ Wt,
    const float* __restrict__ bt)
{
    extern __shared__ uint32_t sm[];
    uint32_t* sX = sm;
    uint32_t* sW = sm + 128 * PJS;

    const int b = blockIdx.y;
    const int n0 = blockIdx.x * 128;
    const int tid = threadIdx.x;
    const int lane = tid & 31, warp = tid >> 5;
    const int g = lane >> 2, t = lane & 3;
    const int wm = warp >> 2, wn = warp & 3;

    for (int idx = tid; idx < 96 * 128; idx += 256) {
        int c2 = idx >> 7, n = idx & 127;
        float v0 = x[((size_t)(b * CIN + 2 * c2)) * NPIX + n0 + n];
        float v1 = x[((size_t)(b * CIN + 2 * c2 + 1)) * NPIX + n0 + n];
        sX[n * PJS + c2] = pack_h(v0, v1);
    }

    for (int oblk = 0; oblk < 3; oblk++) {
        const int o0 = oblk * 96;
        for (int idx = tid; idx < 96 * 96; idx += 256) {
            int o = idx / 96, w = idx % 96;
            float2 v = *reinterpret_cast<const float2*>(Wt + (size_t)(o0 + o) * CIN + 2 * w);
            sW[o * PJS + w] = pack_h(v.x, v.y);
        }
        __syncthreads();

        float acc[3][4][4] = {};
        #pragma unroll
        for (int ch = 0; ch < 12; ch++) {
            const int cw = ch * 8;
            uint32_t A[3][4], B[4][2];
            #pragma unroll
            for (int mi = 0; mi < 3; mi++) {
                int r = wm * 48 + mi * 16 + g;
                A[mi][0] = sW[r * PJS + cw + t];
                A[mi][1] = sW[(r + 8) * PJS + cw + t];
                A[mi][2] = sW[r * PJS + cw + t + 4];
                A[mi][3] = sW[(r + 8) * PJS + cw + t + 4];
            }
            #pragma unroll
            for (int ni = 0; ni < 4; ni++) {
                int n = wn * 32 + ni * 8 + g;
                B[ni][0] = sX[n * PJS + cw + t];
                B[ni][1] = sX[n * PJS + cw + t + 4];
            }
            #pragma unroll
            for (int mi = 0; mi < 3; mi++)
                #pragma unroll
                for (int ni = 0; ni < 4; ni++)
                    mma16(acc[mi][ni], A[mi], B[ni]);
        }
        __syncthreads();

        if (oblk == 1) {
            #pragma unroll
            for (int mi = 0; mi < 3; mi++) {
                int c = wm * 48 + mi * 16 + g;
                float b0 = bt[96 + c], b1 = bt[96 + c + 8];
                #pragma unroll
                for (int ni = 0; ni < 4; ni++) {
                    int col = wn * 32 + ni * 8 + 2 * t;
                    size_t base = ((size_t)(b * LAT + c)) * NPIX + n0 + col;
                    *reinterpret_cast<uint32_t*>(&g_v[base]) =
                        pack_h(acc[mi][ni][0] + b0, acc[mi][ni][1] + b0);
                    *reinterpret_cast<uint32_t*>(&g_v[base + 8 * NPIX]) =
                        pack_h(acc[mi][ni][2] + b1, acc[mi][ni][3] + b1);
                }
            }
        } else {
            const float scale = (oblk == 2) ? SCALE_K : 1.0f;
            __half* sT = reinterpret_cast<__half*>(sW);
            #pragma unroll
            for (int mi = 0; mi < 3; mi++) {
                int c = wm * 48 + mi * 16 + g;
                float b0 = bt[o0 + c], b1 = bt[o0 + c + 8];
                #pragma unroll
                for (int ni = 0; ni < 4; ni++) {
                    int n = wn * 32 + ni * 8 + 2 * t;
                    sT[n * 104 + c]           = __float2half((acc[mi][ni][0] + b0) * scale);
                    sT[(n + 1) * 104 + c]     = __float2half((acc[mi][ni][1] + b0) * scale);
                    sT[n * 104 + c + 8]       = __float2half((acc[mi][ni][2] + b1) * scale);
                    sT[(n + 1) * 104 + c + 8] = __float2half((acc[mi][ni][3] + b1) * scale);
                }
            }
            __syncthreads();
            const int qko = (oblk == 0) ? 0 : 96;
            for (int idx = tid; idx < 128 * 12; idx += 256) {
                int n = idx / 12, u = idx % 12;
                uint4 v = *reinterpret_cast<uint4*>(sT + n * 104 + u * 8);
                *reinterpret_cast<uint4*>(
                    g_qk + ((size_t)(b * NPIX + n0 + n)) * 192 + qko + u * 8) = v;
            }
        }
        __syncthreads();
    }
}

// ---------------------------------------------------------------------------
// Kernel 2: fused flash attention + output projection + residual.
// 512 threads, 16 warps: pair p=w>>1 owns kq rows [16p,16p+16); half h=w&1
// owns q cols [64h,64h+64). Partial O/L per warp; one cross-pair reduction
// at the end. 4 warps/SMSP for latency hiding. grid (32 kq-blocks, 8 batch).
// ---------------------------------------------------------------------------
#define LKW 52     // K/Q tile row stride words (LDSM conflict-free)
#define LVW 68     // V tile row stride words (LDSM conflict-free)
#define AQT (128 * LKW)                      // 6656 (K region end)
#define AVT (AQT + 2 * 128 * LKW)            // 19968
#define ASL (AVT + 2 * 96 * LVW)             // 33024
#define ATTN_WORDS (ASL + 384)               // sLh[2][128] + sLinv[128]
#define ATTN_SMEM_BYTES (ATTN_WORDS * 4)     // 133632
#define NBQ (16 * LKW * 4)                   // bytes per 16 Q rows
#define MIV (16 * LVW * 4)                   // bytes per 16 V rows
#define OBS 132                              // Obuf row stride (floats)

#define ATHR 512

__global__ __launch_bounds__(ATHR, 1) void attn_kernel(
    const float* __restrict__ x, const float* __restrict__ Wd,
    const float* __restrict__ bd, float* __restrict__ out)
{
    extern __shared__ uint32_t sm[];
    uint32_t* KT = sm;              // [128 kq][96 c]; reused for att^T after loop
    uint32_t* QT = sm + AQT;        // 2 x [128 q][96 c]; reused as Obuf, then Wd
    uint32_t* VT = sm + AVT;        // 2 x [96 c][128 q]
    float* sLh   = reinterpret_cast<float*>(sm + ASL);  // [2][128]
    float* sLinv = sLh + 256;                            // [128]

    const int b = blockIdx.y, k0 = blockIdx.x * 128;
    const int tid = threadIdx.x;
    const int lane = tid & 31, w = tid >> 5;   // warp 0..15
    const int p = w >> 1, h = w & 1;
    const int g = lane >> 2, t = lane & 3;

    const __half* QK = g_qk + (size_t)b * NPIX * 192;
    const __half* Vg = g_v + (size_t)b * LAT * NPIX;

    const uint32_t smb = (uint32_t)__cvta_generic_to_shared(sm);
    const int lr16 = lane & 15;
    const int lhi4 = (lane >> 4) * 4;
    const int brow = ((lane >> 4) << 3) + (lane & 7);
    const int bkhi = ((lane >> 3) & 1) * 4;

    const uint32_t aK  = smb + (((p * 16 + lr16) * LKW) + lhi4) * 4;
    const uint32_t bQ0 = smb + AQT * 4 + (((h * 64 + brow) * LKW) + bkhi) * 4;
    const uint32_t aV0 = smb + AVT * 4 + ((lr16 * LVW) + lhi4) * 4 + (uint32_t)h * 128;

    // persistent K tile: 128 rows x 12 x 16B
    for (int idx = tid; idx < 128 * 12; idx += ATHR) {
        int r = idx / 12, u = idx % 12;
        cpa16(KT + r * LKW + 4 * u, QK + (size_t)(k0 + r) * 192 + 96 + 8 * u);
    }
    // prefetch Q/V buffer 0
    for (int idx = tid; idx < 128 * 12; idx += ATHR) {
        int r = idx / 12, u = idx % 12;
        cpa16(QT + r * LKW + 4 * u, QK + (size_t)r * 192 + 8 * u);
    }
    for (int idx = tid; idx < 96 * 16; idx += ATHR) {
        int r = idx / 16, u = idx % 16;
        cpa16(VT + r * LVW + 4 * u, Vg + (size_t)r * NPIX + 8 * u);
    }
    CP_COMMIT();

    float O[6][2][4] = {};          // partial over this warp's q-half
    float L0 = 0.f, L1 = 0.f;       // partial row sums (rows 16p+g, 16p+8+g)

    for (int it = 0; it < 32; it++) {
        const uint32_t bufQ = (uint32_t)(it & 1) * 128 * LKW * 4;
        const uint32_t bufV = (uint32_t)(it & 1) * 96 * LVW * 4;
        CP_WAIT0();
        __syncthreads();

        if (it + 1 < 32) {
            const int q1 = (it + 1) * 128;
            uint32_t* Qd = QT + ((it + 1) & 1) * 128 * LKW;
            uint32_t* Vd = VT + ((it + 1) & 1) * 96 * LVW;
            for (int idx = tid; idx < 128 * 12; idx += ATHR) {
                int r = idx / 12, u = idx % 12;
                cpa16(Qd + r * LKW + 4 * u, QK + (size_t)(q1 + r) * 192 + 8 * u);
            }
            for (int idx = tid; idx < 96 * 16; idx += ATHR) {
                int r = idx / 16, u = idx % 16;
                cpa16(Vd + r * LVW + 4 * u, Vg + (size_t)r * NPIX + q1 + 8 * u);
            }
        }
        CP_COMMIT();

        // ---- GEMM1: S[16 kq][64 q-half] per warp, k = 96, f16 accum ----
        uint32_t S16[8][2] = {};
        #pragma unroll
        for (int ch = 0; ch < 6; ch++) {
            const uint32_t cwb = (uint32_t)ch * 32;
            uint32_t A[4];
            ldsm4(A, aK + cwb);
            #pragma unroll
            for (int nb = 0; nb < 4; nb++) {
                uint32_t Bp[4];
                ldsm4(Bp, bQ0 + bufQ + (uint32_t)nb * NBQ + cwb);
                mma16h(S16[2 * nb],     A, &Bp[0]);
                mma16h(S16[2 * nb + 1], A, &Bp[2]);
            }
        }

        // ---- P = exp2(S) in place; partial L sums ----
        uint32_t a0 = 0, a1 = 0;
        #pragma unroll
        for (int nq = 0; nq < 8; nq++) {
            S16[nq][0] = hex2(S16[nq][0]);
            S16[nq][1] = hex2(S16[nq][1]);
            a0 = hadd2(a0, S16[nq][0]);
            a1 = hadd2(a1, S16[nq][1]);
        }
        L0 += h2sum(a0);
        L1 += h2sum(a1);

        // ---- GEMM2: O[96 c][16 kq] += V P^T over q-half (4 chunks) ----
        #pragma unroll
        for (int ch = 0; ch < 4; ch++) {
            const uint32_t cwb = (uint32_t)ch * 32;
            uint32_t Bn0[2] = { S16[2 * ch][0], S16[2 * ch + 1][0] };
            uint32_t Bn1[2] = { S16[2 * ch][1], S16[2 * ch + 1][1] };
            #pragma unroll
            for (int mi = 0; mi < 6; mi++) {
                uint32_t A[4];
                ldsm4(A, aV0 + bufV + (uint32_t)mi * MIV + cwb);
                mma16(O[mi][0], A, Bn0);
                mma16(O[mi][1], A, Bn1);
            }
        }
    }

    // ==== cross-pair reduction + epilogue ====
    __syncthreads();   // all GEMM reads of KT/QT/VT done

    // partial L per warp (sum over its q-half), reduced across t
    L0 = rsum4(L0);
    L1 = rsum4(L1);
    if (t == 0) {
        sLh[h * 128 + p * 16 + g]     = L0;
        sLh[h * 128 + p * 16 + 8 + g] = L1;
    }

    // h==0 warps dump partial O into Obuf (QT region, stride OBS floats)
    float* Obuf = reinterpret_cast<float*>(QT);
    if (h == 0) {
        #pragma unroll
        for (int mi = 0; mi < 6; mi++) {
            int c = mi * 16 + g;
            #pragma unroll
            for (int ni = 0; ni < 2; ni++) {
                int col = p * 16 + ni * 8 + 2 * t;
                *reinterpret_cast<float2*>(&Obuf[c * OBS + col]) =
                    make_float2(O[mi][ni][0], O[mi][ni][1]);
                *reinterpret_cast<float2*>(&Obuf[(c + 8) * OBS + col]) =
                    make_float2(O[mi][ni][2], O[mi][ni][3]);
            }
        }
    }
    __syncthreads();
    if (tid < 128) sLinv[tid] = frcp(sLh[tid] + sLh[128 + tid]);
    __syncthreads();

    // h==1 warps: combine halves, normalize, stage att^T fp16 [128 kq][96 c]
    __half* sT = reinterpret_cast<__half*>(sm);      // stride 104 fp16 (52 words)
    if (h == 1) {
        #pragma unroll
        for (int mi = 0; mi < 6; mi++) {
            int c = mi * 16 + g;
            #pragma unroll
            for (int ni = 0; ni < 2; ni++) {
                int col = p * 16 + ni * 8 + 2 * t;
                float rE = sLinv[col], rO = sLinv[col + 1];
                float2 o0 = *reinterpret_cast<float2*>(&Obuf[c * OBS + col]);
                float2 o1 = *reinterpret_cast<float2*>(&Obuf[(c + 8) * OBS + col]);
                sT[col * 104 + c]           = __float2half((O[mi][ni][0] + o0.x) * rE);
                sT[(col + 1) * 104 + c]     = __float2half((O[mi][ni][1] + o0.y) * rO);
                sT[col * 104 + c + 8]       = __float2half((O[mi][ni][2] + o1.x) * rE);
                sT[(col + 1) * 104 + c + 8] = __float2half((O[mi][ni][3] + o1.y) * rO);
            }
        }
    }
    __syncthreads();

    // stage Wd fp16 [192 o][96 c] into QT region (Obuf dead)
    uint32_t* sWd = QT;
    for (int idx = tid; idx < 192 * 48; idx += ATHR) {
        int o = idx / 48, u = idx % 48;
        float2 v = *reinterpret_cast<const float2*>(Wd + (size_t)o * LAT + 2 * u);
        sWd[o * LKW + u] = pack_h(v.x, v.y);
    }
    __syncthreads();

    // ---- fused output projection: out = Wd @ att + bd + x (16 warps, 4x4) ----
    const int wm = w >> 2, wn = w & 3;
    uint32_t aW[3], bA[2];
    #pragma unroll
    for (int mi = 0; mi < 3; mi++)
        aW[mi] = smb + AQT * 4 + (((wm * 48 + mi * 16 + lr16) * LKW) + lhi4) * 4;
    #pragma unroll
    for (int p2 = 0; p2 < 2; p2++)
        bA[p2] = smb + (((wn * 32 + p2 * 16 + brow) * LKW) + bkhi) * 4;

    float acc[3][4][4] = {};
    #pragma unroll
    for (int ch = 0; ch < 6; ch++) {
        const uint32_t cwb = (uint32_t)ch * 32;
        uint32_t A[3][4], Bp[2][4];
        #pragma unroll
        for (int mi = 0; mi < 3; mi++) ldsm4(A[mi], aW[mi] + cwb);
        #pragma unroll
        for (int p2 = 0; p2 < 2; p2++) ldsm4(Bp[p2], bA[p2] + cwb);
        #pragma unroll
        for (int mi = 0; mi < 3; mi++) {
            mma16(acc[mi][0], A[mi], &Bp[0][0]);
            mma16(acc[mi][1], A[mi], &Bp[0][2]);
            mma16(acc[mi][2], A[mi], &Bp[1][0]);
            mma16(acc[mi][3], A[mi], &Bp[1][2]);
        }
    }

    #pragma unroll
    for (int mi = 0; mi < 3; mi++) {
        int o = wm * 48 + mi * 16 + g;
        float b0 = bd[o], b1 = bd[o + 8];
        #pragma unroll
        for (int ni = 0; ni < 4; ni++) {
            int col = k0 + wn * 32 + ni * 8 + 2 * t;
            size_t i0 = ((size_t)(b * CIN + o)) * NPIX + col;
            float2 xr0 = *reinterpret_cast<const float2*>(x + i0);
            float2 v0 = make_float2(acc[mi][ni][0] + b0 + xr0.x,
                                    acc[mi][ni][1] + b0 + xr0.y);
            *reinterpret_cast<float2*>(out + i0) = v0;
            size_t i1 = i0 + (size_t)8 * NPIX;
            float2 xr1 = *reinterpret_cast<const float2*>(x + i1);
            float2 v1 = make_float2(acc[mi][ni][2] + b1 + xr1.x,
                                    acc[mi][ni][3] + b1 + xr1.y);
            *reinterpret_cast<float2*>(out + i1) = v1;
        }
    }
}

// ---------------------------------------------------------------------------
extern "C" void kernel_launch(void* const* d_in, const int* in_sizes, int n_in,
                              void* d_out, int out_size)
{
    const float* x  = (const float*)d_in[0];
    const float* Wt = (const float*)d_in[1];
    const float* bt = (const float*)d_in[2];
    const float* Wd = (const float*)d_in[3];
    const float* bd = (const float*)d_in[4];
    float* out = (float*)d_out;

    cudaFuncSetAttribute(proj_kernel,
        cudaFuncAttributeMaxDynamicSharedMemorySize, PROJ_SMEM_BYTES);
    cudaFuncSetAttribute(attn_kernel,
        cudaFuncAttributeMaxDynamicSharedMemorySize, ATTN_SMEM_BYTES);

    proj_kernel<<<dim3(32, BATCH), 256, PROJ_SMEM_BYTES>>>(x, Wt, bt);
    attn_kernel<<<dim3(32, BATCH), ATHR, ATTN_SMEM_BYTES>>>(x, Wd, bd, out);
}

// round 17
// speedup vs baseline: 1.2157x; 1.2157x over previous
#include <cuda_runtime.h>
#include <cuda_fp16.h>
#include <cstdint>

#define BATCH 8
#define CIN   192
#define NPIX  4096
#define LAT   96
// log2(e) / sqrt(96): fold softmax scale + base-2 exp into K
#define SCALE_K 0.14724450f

// Static device scratch (allocation-free) — fp16
__device__ __half g_qk[(size_t)BATCH * NPIX * 192]; // [b][n][0:96=Q, 96:192=K*SCALE_K]
__device__ __half g_v [(size_t)BATCH * LAT * NPIX]; // [b][c][n]

// ---------------------------------------------------------------------------
// helpers
// ---------------------------------------------------------------------------
__device__ __forceinline__ void mma16(float d[4], const uint32_t a[4], const uint32_t b[2]) {
    asm volatile(
        "mma.sync.aligned.m16n8k16.row.col.f32.f16.f16.f32 "
        "{%0,%1,%2,%3}, {%4,%5,%6,%7}, {%8,%9}, {%0,%1,%2,%3};"
        : "+f"(d[0]), "+f"(d[1]), "+f"(d[2]), "+f"(d[3])
        : "r"(a[0]), "r"(a[1]), "r"(a[2]), "r"(a[3]), "r"(b[0]), "r"(b[1]));
}
__device__ __forceinline__ void mma16h(uint32_t d[2], const uint32_t a[4], const uint32_t b[2]) {
    asm volatile(
        "mma.sync.aligned.m16n8k16.row.col.f16.f16.f16.f16 "
        "{%0,%1}, {%2,%3,%4,%5}, {%6,%7}, {%0,%1};"
        : "+r"(d[0]), "+r"(d[1])
        : "r"(a[0]), "r"(a[1]), "r"(a[2]), "r"(a[3]), "r"(b[0]), "r"(b[1]));
}
__device__ __forceinline__ void ldsm4(uint32_t r[4], uint32_t addr) {
    asm volatile("ldmatrix.sync.aligned.m8n8.x4.shared.b16 {%0,%1,%2,%3}, [%4];"
        : "=r"(r[0]), "=r"(r[1]), "=r"(r[2]), "=r"(r[3]) : "r"(addr));
}
__device__ __forceinline__ float frcp(float x) {
    float r; asm("rcp.approx.ftz.f32 %0, %1;" : "=f"(r) : "f"(x));
    return r * (2.0f - x * r);
}
__device__ __forceinline__ uint32_t pack_h(float lo, float hi) {
    __half2 h = __floats2half2_rn(lo, hi);
    return *reinterpret_cast<uint32_t*>(&h);
}
__device__ __forceinline__ uint32_t hex2(uint32_t a) {
    uint32_t r; asm("ex2.approx.f16x2 %0, %1;" : "=r"(r) : "r"(a)); return r;
}
__device__ __forceinline__ uint32_t hadd2(uint32_t a, uint32_t b) {
    uint32_t r; asm("add.f16x2 %0, %1, %2;" : "=r"(r) : "r"(a), "r"(b)); return r;
}
__device__ __forceinline__ float h2sum(uint32_t a) {
    __half2 h = *reinterpret_cast<__half2*>(&a);
    return __low2float(h) + __high2float(h);
}
__device__ __forceinline__ void cpa16(void* dst, const void* src) {
    uint32_t d = (uint32_t)__cvta_generic_to_shared(dst);
    asm volatile("cp.async.cg.shared.global [%0], [%1], 16;" :: "r"(d), "l"(src));
}
#define CP_COMMIT() asm volatile("cp.async.commit_group;")
#define CP_WAIT0()  asm volatile("cp.async.wait_group 0;")
__device__ __forceinline__ float rsum4(float v) {
    v += __shfl_xor_sync(0xffffffffu, v, 1);
    v += __shfl_xor_sync(0xffffffffu, v, 2);
    return v;
}

// ---------------------------------------------------------------------------
// Kernel 1: projection t = Wt@x + bt (fp16 mma, fp32 accum). (unchanged)
// ---------------------------------------------------------------------------
#define PJS 100
#define PROJ_SMEM_BYTES ((128 * PJS + 96 * PJS) * 4)   // 89600

__global__ __launch_bounds__(256, 2) void proj_kernel(
    const float* __restrict__ x, const float* __restrict__ Wt,
    const float* __restrict__ bt)
{
    extern __shared__ uint32_t sm[];
    uint32_t* sX = sm;
    uint32_t* sW = sm + 128 * PJS;

    const int b = blockIdx.y;
    const int n0 = blockIdx.x * 128;
    const int tid = threadIdx.x;
    const int lane = tid & 31, warp = tid >> 5;
    const int g = lane >> 2, t = lane & 3;
    const int wm = warp >> 2, wn = warp & 3;

    for (int idx = tid; idx < 96 * 128; idx += 256) {
        int c2 = idx >> 7, n = idx & 127;
        float v0 = x[((size_t)(b * CIN + 2 * c2)) * NPIX + n0 + n];
        float v1 = x[((size_t)(b * CIN + 2 * c2 + 1)) * NPIX + n0 + n];
        sX[n * PJS + c2] = pack_h(v0, v1);
    }

    for (int oblk = 0; oblk < 3; oblk++) {
        const int o0 = oblk * 96;
        for (int idx = tid; idx < 96 * 96; idx += 256) {
            int o = idx / 96, w = idx % 96;
            float2 v = *reinterpret_cast<const float2*>(Wt + (size_t)(o0 + o) * CIN + 2 * w);
            sW[o * PJS + w] = pack_h(v.x, v.y);
        }
        __syncthreads();

        float acc[3][4][4] = {};
        #pragma unroll
        for (int ch = 0; ch < 12; ch++) {
            const int cw = ch * 8;
            uint32_t A[3][4], B[4][2];
            #pragma unroll
            for (int mi = 0; mi < 3; mi++) {
                int r = wm * 48 + mi * 16 + g;
                A[mi][0] = sW[r * PJS + cw + t];
                A[mi][1] = sW[(r + 8) * PJS + cw + t];
                A[mi][2] = sW[r * PJS + cw + t + 4];
                A[mi][3] = sW[(r + 8) * PJS + cw + t + 4];
            }
            #pragma unroll
            for (int ni = 0; ni < 4; ni++) {
                int n = wn * 32 + ni * 8 + g;
                B[ni][0] = sX[n * PJS + cw + t];
                B[ni][1] = sX[n * PJS + cw + t + 4];
            }
            #pragma unroll
            for (int mi = 0; mi < 3; mi++)
                #pragma unroll
                for (int ni = 0; ni < 4; ni++)
                    mma16(acc[mi][ni], A[mi], B[ni]);
        }
        __syncthreads();

        if (oblk == 1) {
            #pragma unroll
            for (int mi = 0; mi < 3; mi++) {
                int c = wm * 48 + mi * 16 + g;
                float b0 = bt[96 + c], b1 = bt[96 + c + 8];
                #pragma unroll
                for (int ni = 0; ni < 4; ni++) {
                    int col = wn * 32 + ni * 8 + 2 * t;
                    size_t base = ((size_t)(b * LAT + c)) * NPIX + n0 + col;
                    *reinterpret_cast<uint32_t*>(&g_v[base]) =
                        pack_h(acc[mi][ni][0] + b0, acc[mi][ni][1] + b0);
                    *reinterpret_cast<uint32_t*>(&g_v[base + 8 * NPIX]) =
                        pack_h(acc[mi][ni][2] + b1, acc[mi][ni][3] + b1);
                }
            }
        } else {
            const float scale = (oblk == 2) ? SCALE_K : 1.0f;
            __half* sT = reinterpret_cast<__half*>(sW);
            #pragma unroll
            for (int mi = 0; mi < 3; mi++) {
                int c = wm * 48 + mi * 16 + g;
                float b0 = bt[o0 + c], b1 = bt[o0 + c + 8];
                #pragma unroll
                for (int ni = 0; ni < 4; ni++) {
                    int n = wn * 32 + ni * 8 + 2 * t;
                    sT[n * 104 + c]           = __float2half((acc[mi][ni][0] + b0) * scale);
                    sT[(n + 1) * 104 + c]     = __float2half((acc[mi][ni][1] + b0) * scale);
                    sT[n * 104 + c + 8]       = __float2half((acc[mi][ni][2] + b1) * scale);
                    sT[(n + 1) * 104 + c + 8] = __float2half((acc[mi][ni][3] + b1) * scale);
                }
            }
            __syncthreads();
            const int qko = (oblk == 0) ? 0 : 96;
            for (int idx = tid; idx < 128 * 12; idx += 256) {
                int n = idx / 12, u = idx % 12;
                uint4 v = *reinterpret_cast<uint4*>(sT + n * 104 + u * 8);
                *reinterpret_cast<uint4*>(
                    g_qk + ((size_t)(b * NPIX + n0 + n)) * 192 + qko + u * 8) = v;
            }
        }
        __syncthreads();
    }
}

// ---------------------------------------------------------------------------
// Kernel 2: fused flash attention + output projection + residual.
// kq-tile 256, grid (16, 8) = 128 CTAs = SINGLE WAVE. Warp w owns kq rows
// [32w, 32w+32) (2 m-blocks), full q width. Per-iteration fixed costs
// (barrier, staging, cp wait) amortize over 2x tensor work; Q/V traffic per
// unit work halves. f16-accum GEMM1, in-place f16x2 exp, fp32-accum GEMM2.
// ---------------------------------------------------------------------------
#define LKW 52     // K/Q tile row stride words (LDSM conflict-free)
#define LVW 68     // V tile row stride words (LDSM conflict-free)
#define AKTW (256 * LKW)                     // 13312 (K region words)
#define AQT AKTW                             // Q buffers start
#define AVT (AQT + 2 * 128 * LKW)            // 26624
#define ATTN_WORDS (AVT + 2 * 96 * LVW + 64) // 39744 words
#define ATTN_SMEM_BYTES (ATTN_WORDS * 4)     // 158976
#define NBQ (16 * LKW * 4)                   // bytes per 16 Q rows
#define MIV (16 * LVW * 4)                   // bytes per 16 V rows

__global__ __launch_bounds__(256, 1) void attn_kernel(
    const float* __restrict__ x, const float* __restrict__ Wd,
    const float* __restrict__ bd, float* __restrict__ out)
{
    extern __shared__ uint32_t sm[];
    uint32_t* KT = sm;              // [256 kq][96 c]; reused for att^T after loop
    uint32_t* QT = sm + AQT;        // 2 x [128 q][96 c]; reused for Wd after loop
    uint32_t* VT = sm + AVT;        // 2 x [96 c][128 q]

    const int b = blockIdx.y, k0 = blockIdx.x * 256;
    const int tid = threadIdx.x;
    const int lane = tid & 31, w = tid >> 5;   // warp 0..7
    const int g = lane >> 2, t = lane & 3;

    const __half* QK = g_qk + (size_t)b * NPIX * 192;
    const __half* Vg = g_v + (size_t)b * LAT * NPIX;

    const uint32_t smb = (uint32_t)__cvta_generic_to_shared(sm);
    const int lr16 = lane & 15;
    const int lhi4 = (lane >> 4) * 4;
    const int brow = ((lane >> 4) << 3) + (lane & 7);
    const int bkhi = ((lane >> 3) & 1) * 4;

    uint32_t aK[2];
    #pragma unroll
    for (int m2 = 0; m2 < 2; m2++)
        aK[m2] = smb + (((w * 32 + m2 * 16 + lr16) * LKW) + lhi4) * 4;
    const uint32_t bQ0 = smb + AQT * 4 + ((brow * LKW) + bkhi) * 4;
    const uint32_t aV0 = smb + AVT * 4 + ((lr16 * LVW) + lhi4) * 4;

    // persistent K tile: 256 rows x 12 x 16B
    for (int idx = tid; idx < 256 * 12; idx += 256) {
        int r = idx / 12, u = idx % 12;
        cpa16(KT + r * LKW + 4 * u, QK + (size_t)(k0 + r) * 192 + 96 + 8 * u);
    }
    // prefetch Q/V buffer 0
    for (int idx = tid; idx < 128 * 12; idx += 256) {
        int r = idx / 12, u = idx % 12;
        cpa16(QT + r * LKW + 4 * u, QK + (size_t)r * 192 + 8 * u);
    }
    for (int idx = tid; idx < 96 * 16; idx += 256) {
        int r = idx / 16, u = idx % 16;
        cpa16(VT + r * LVW + 4 * u, Vg + (size_t)r * NPIX + 8 * u);
    }
    CP_COMMIT();

    float O[6][4][4] = {};          // [c m-block][kq n-block: 2m2+{0,1}][frag]
    float L[2][2] = {};             // rows 32w+16m2+{g, 8+g}

    for (int it = 0; it < 32; it++) {
        const uint32_t bufQ = (uint32_t)(it & 1) * 128 * LKW * 4;
        const uint32_t bufV = (uint32_t)(it & 1) * 96 * LVW * 4;
        CP_WAIT0();
        __syncthreads();

        if (it + 1 < 32) {
            const int q1 = (it + 1) * 128;
            uint32_t* Qd = QT + ((it + 1) & 1) * 128 * LKW;
            uint32_t* Vd = VT + ((it + 1) & 1) * 96 * LVW;
            for (int idx = tid; idx < 128 * 12; idx += 256) {
                int r = idx / 12, u = idx % 12;
                cpa16(Qd + r * LKW + 4 * u, QK + (size_t)(q1 + r) * 192 + 8 * u);
            }
            for (int idx = tid; idx < 96 * 16; idx += 256) {
                int r = idx / 16, u = idx % 16;
                cpa16(Vd + r * LVW + 4 * u, Vg + (size_t)r * NPIX + q1 + 8 * u);
            }
        }
        CP_COMMIT();

        // ---- GEMM1: S[32 kq][128 q] per warp, k = 96, f16 accumulators ----
        uint32_t S16[2][16][2] = {};
        #pragma unroll
        for (int ch = 0; ch < 6; ch++) {
            const uint32_t cwb = (uint32_t)ch * 32;
            uint32_t A[2][4];
            ldsm4(A[0], aK[0] + cwb);
            ldsm4(A[1], aK[1] + cwb);
            #pragma unroll
            for (int nb = 0; nb < 8; nb++) {
                uint32_t Bp[4];
                ldsm4(Bp, bQ0 + bufQ + (uint32_t)nb * NBQ + cwb);
                #pragma unroll
                for (int m2 = 0; m2 < 2; m2++) {
                    mma16h(S16[m2][2 * nb],     A[m2], &Bp[0]);
                    mma16h(S16[m2][2 * nb + 1], A[m2], &Bp[2]);
                }
            }
        }

        // ---- P = exp2(S) in place; L sums via HADD2 tree ----
        #pragma unroll
        for (int m2 = 0; m2 < 2; m2++) {
            uint32_t a0 = 0, a1 = 0;
            #pragma unroll
            for (int nq = 0; nq < 16; nq++) {
                S16[m2][nq][0] = hex2(S16[m2][nq][0]);
                S16[m2][nq][1] = hex2(S16[m2][nq][1]);
                a0 = hadd2(a0, S16[m2][nq][0]);
                a1 = hadd2(a1, S16[m2][nq][1]);
            }
            L[m2][0] += h2sum(a0);
            L[m2][1] += h2sum(a1);
        }

        // ---- GEMM2: O[96 c][32 kq] += V P^T, k = 128 (8 chunks) ----
        #pragma unroll
        for (int ch = 0; ch < 8; ch++) {
            const uint32_t cwb = (uint32_t)ch * 32;
            uint32_t Bn[2][2][2];
            #pragma unroll
            for (int m2 = 0; m2 < 2; m2++) {
                Bn[m2][0][0] = S16[m2][2 * ch][0];     Bn[m2][0][1] = S16[m2][2 * ch + 1][0];
                Bn[m2][1][0] = S16[m2][2 * ch][1];     Bn[m2][1][1] = S16[m2][2 * ch + 1][1];
            }
            #pragma unroll
            for (int mi = 0; mi < 6; mi++) {
                uint32_t A[4];
                ldsm4(A, aV0 + bufV + (uint32_t)mi * MIV + cwb);
                #pragma unroll
                for (int m2 = 0; m2 < 2; m2++) {
                    mma16(O[mi][2 * m2],     A, Bn[m2][0]);
                    mma16(O[mi][2 * m2 + 1], A, Bn[m2][1]);
                }
            }
        }
    }

    // ---- normalization factors: warp-local ----
    float rA[2], rB[2], rC[2], rD[2];
    #pragma unroll
    for (int m2 = 0; m2 < 2; m2++) {
        float l0 = rsum4(L[m2][0]);
        float l1 = rsum4(L[m2][1]);
        rA[m2] = frcp(__shfl_sync(0xffffffffu, l0, 8 * t));
        rB[m2] = frcp(__shfl_sync(0xffffffffu, l0, 8 * t + 4));
        rC[m2] = frcp(__shfl_sync(0xffffffffu, l1, 8 * t));
        rD[m2] = frcp(__shfl_sync(0xffffffffu, l1, 8 * t + 4));
    }

    // ---- stage normalized att^T fp16 [256 kq][96 c] in KT region ----
    __syncthreads();   // all warps done reading KT/QT/VT
    __half* sT = reinterpret_cast<__half*>(sm);      // stride 104 fp16 (52 words)
    #pragma unroll
    for (int m2 = 0; m2 < 2; m2++) {
        const int r0 = w * 32 + m2 * 16 + 2 * t;
        #pragma unroll
        for (int mi = 0; mi < 6; mi++) {
            int c = mi * 16 + g;
            sT[r0 * 104 + c]            = __float2half(O[mi][2 * m2][0] * rA[m2]);
            sT[(r0 + 1) * 104 + c]      = __float2half(O[mi][2 * m2][1] * rB[m2]);
            sT[r0 * 104 + c + 8]        = __float2half(O[mi][2 * m2][2] * rA[m2]);
            sT[(r0 + 1) * 104 + c + 8]  = __float2half(O[mi][2 * m2][3] * rB[m2]);
            sT[(r0 + 8) * 104 + c]      = __float2half(O[mi][2 * m2 + 1][0] * rC[m2]);
            sT[(r0 + 9) * 104 + c]      = __float2half(O[mi][2 * m2 + 1][1] * rD[m2]);
            sT[(r0 + 8) * 104 + c + 8]  = __float2half(O[mi][2 * m2 + 1][2] * rC[m2]);
            sT[(r0 + 9) * 104 + c + 8]  = __float2half(O[mi][2 * m2 + 1][3] * rD[m2]);
        }
    }
    uint32_t* sWd = QT;   // [192 o][96 c] fp16, stride 52 words
    for (int idx = tid; idx < 192 * 48; idx += 256) {
        int o = idx / 48, u = idx % 48;
        float2 v = *reinterpret_cast<const float2*>(Wd + (size_t)o * LAT + 2 * u);
        sWd[o * LKW + u] = pack_h(v.x, v.y);
    }
    __syncthreads();

    // ---- fused output projection over two 128-col halves ----
    const int wm = w >> 2, wn = w & 3;
    uint32_t aW[6];
    #pragma unroll
    for (int mi = 0; mi < 6; mi++)
        aW[mi] = smb + AQT * 4 + (((wm * 96 + mi * 16 + lr16) * LKW) + lhi4) * 4;

    for (int half = 0; half < 2; half++) {
        uint32_t bA[2];
        #pragma unroll
        for (int p = 0; p < 2; p++)
            bA[p] = smb + (((half * 128 + wn * 32 + p * 16 + brow) * LKW) + bkhi) * 4;

        float acc[6][4][4] = {};
        #pragma unroll
        for (int ch = 0; ch < 6; ch++) {
            const uint32_t cwb = (uint32_t)ch * 32;
            uint32_t A[6][4], Bp[2][4];
            #pragma unroll
            for (int mi = 0; mi < 6; mi++) ldsm4(A[mi], aW[mi] + cwb);
            #pragma unroll
            for (int p = 0; p < 2; p++) ldsm4(Bp[p], bA[p] + cwb);
            #pragma unroll
            for (int mi = 0; mi < 6; mi++) {
                mma16(acc[mi][0], A[mi], &Bp[0][0]);
                mma16(acc[mi][1], A[mi], &Bp[0][2]);
                mma16(acc[mi][2], A[mi], &Bp[1][0]);
                mma16(acc[mi][3], A[mi], &Bp[1][2]);
            }
        }

        #pragma unroll
        for (int mi = 0; mi < 6; mi++) {
            int o = wm * 96 + mi * 16 + g;
            float b0 = bd[o], b1 = bd[o + 8];
            #pragma unroll
            for (int ni = 0; ni < 4; ni++) {
                int col = k0 + half * 128 + wn * 32 + ni * 8 + 2 * t;
                size_t i0 = ((size_t)(b * CIN + o)) * NPIX + col;
                float2 xr0 = *reinterpret_cast<const float2*>(x + i0);
                float2 v0 = make_float2(acc[mi][ni][0] + b0 + xr0.x,
                                        acc[mi][ni][1] + b0 + xr0.y);
                *reinterpret_cast<float2*>(out + i0) = v0;
                size_t i1 = i0 + (size_t)8 * NPIX;
                float2 xr1 = *reinterpret_cast<const float2*>(x + i1);
                float2 v1 = make_float2(acc[mi][ni][2] + b1 + xr1.x,
                                        acc[mi][ni][3] + b1 + xr1.y);
                *reinterpret_cast<float2*>(out + i1) = v1;
            }
        }
    }
}

// ---------------------------------------------------------------------------
extern "C" void kernel_launch(void* const* d_in, const int* in_sizes, int n_in,
                              void* d_out, int out_size)
{
    const float* x  = (const float*)d_in[0];
    const float* Wt = (const float*)d_in[1];
    const float* bt = (const float*)d_in[2];
    const float* Wd = (const float*)d_in[3];
    const float* bd = (const float*)d_in[4];
    float* out = (float*)d_out;

    cudaFuncSetAttribute(proj_kernel,
        cudaFuncAttributeMaxDynamicSharedMemorySize, PROJ_SMEM_BYTES);
    cudaFuncSetAttribute(attn_kernel,
        cudaFuncAttributeMaxDynamicSharedMemorySize, ATTN_SMEM_BYTES);

    proj_kernel<<<dim3(32, BATCH), 256, PROJ_SMEM_BYTES>>>(x, Wt, bt);
    attn_kernel<<<dim3(16, BATCH), 256, ATTN_SMEM_BYTES>>>(x, Wd, bd, out);
}